// round 17
// baseline (speedup 1.0000x reference)
#include <cuda_runtime.h>
#include <math.h>

// Spectral solution of 1000 masked-Jacobi steps on 512x512, ONE persistent
// kernel, DST parity butterfly (R13 math). Round 17: OPERAND GENERATION —
// no materialized B or sine basis. G1's A-tile (stencil of x0=exp(...)) is
// computed per-thread straight from X/Y (25 expf); every sine-basis operand
// (STe/STo, S) is regenerated in registers via exact-int-mod sinpif (2-8 per
// thread) BEFORE the stage's grid barrier. Consequences:
//  - G1 has NO cross-CTA dependency -> barrier count 4 -> 3
//  - stage A (sx0 smem, basis tables, g_Be/g_Bo round trip) deleted
//  G1: PE/PO = stencil(X,Y) x STp-gen   256 jobs (64x32, TM4, K=32)  [no bar]
//  G2: Cq = S-gen x (PE+/-PO fused8)    256 jobs (32x32, TM2, K=32)  [bar1]
//  G3: U  = ((sumCq16)#W) x S-gen       256 jobs (32x32, TM2, K=32)  [bar2]
//  G4: out= STp-gen x (U fused4 +/-)    256 jobs (32x64, TM2, K=64)  [bar3]
// W in DS fp32 on CTAs 32..63 between bar1 and G2 (cds ordered by bar1,
// readers ordered by bar2). Two-hop CTA0-aggregated barrier (R13-proven).

#define NCTA 128
#define TPB  512
#define HTPB 256
#define GT   (NCTA * TPB)
#define INV511 (1.0f / 511.0f)

__device__ float g_PE [8 * 512 * 64];   // G1 even-parity K-partials
__device__ float g_PO [8 * 512 * 64];   // G1 odd-parity  K-partials
__device__ float g_Cq [16 * 128 * 128]; // G2 K-partials
__device__ float g_U  [4 * 128 * 512];  // G3 K-partials
__device__ float g_W  [128 * 128];      // signed spectral weights
__device__ float2 g_cds[64];            // cos(pi*i/511), double-single
__device__ unsigned g_bar[NCTA + 1];    // [cta]=arrive, [NCTA]=release

__device__ __forceinline__ unsigned ld_acq(const unsigned* p) {
    unsigned v;
    asm volatile("ld.acquire.gpu.u32 %0, [%1];" : "=r"(v) : "l"(p) : "memory");
    return v;
}
__device__ __forceinline__ void st_rel(unsigned* p, unsigned v) {
    asm volatile("st.release.gpu.u32 [%0], %1;" :: "l"(p), "r"(v) : "memory");
}
__device__ __forceinline__ void bar_named(int id) {
    asm volatile("bar.sync %0, %1;" :: "r"(id), "r"(HTPB) : "memory");
}
__device__ __forceinline__ int modeI(int m) { return (m < 64) ? (m + 1) : (574 - m); }

// Two-hop CTA0-aggregated grid barrier (127 + 127 pollers).
__device__ __forceinline__ void grid_bar(unsigned ep) {
    __syncthreads();
    const int cta = blockIdx.x, tid = threadIdx.x;
    if (cta == 0) {
        if (tid > 0 && tid < NCTA)
            while (ld_acq(&g_bar[tid]) < ep) { }
        __syncthreads();
        if (tid == 0) st_rel(&g_bar[NCTA], ep);
    } else {
        if (tid == 0) {
            st_rel(&g_bar[cta], ep);
            while (ld_acq(&g_bar[NCTA]) < ep) { }
        }
        __syncthreads();
    }
}

// x0 value at flat index (r*512+c): exp(-50*((X-.5)^2+(Y-.5)^2))
__device__ __forceinline__ float gaussv(const float* __restrict__ X,
                                        const float* __restrict__ Y, int idx) {
    float dx = X[idx] - 0.5f, dy = Y[idx] - 0.5f;
    return expf(-50.0f * (dx * dx + dy * dy));
}
// sine basis sin(pi * (ii*pos mod 1022) / 511) via exact integer reduction
__device__ __forceinline__ float sbasis(int ii, int pos) {
    int a = (ii * pos) % 1022;
    return sinpif((float)a * INV511);
}

// ---- double-single helpers ----
struct DS { float hi, lo; };
__device__ __forceinline__ DS ds_renorm(float s, float e) {
    float hi = s + e;
    float lo = e - (hi - s);
    return DS{hi, lo};
}
__device__ __forceinline__ DS ds_add(DS a, DS b) {
    float s = a.hi + b.hi;
    float v = s - a.hi;
    float e = (a.hi - (s - v)) + (b.hi - v);
    return ds_renorm(s, (e + a.lo) + b.lo);
}
__device__ __forceinline__ DS ds_mul(DS a, DS b) {
    float p = a.hi * b.hi;
    float e = fmaf(a.hi, b.hi, -p);
    e = fmaf(a.hi, b.lo, e);
    e = fmaf(a.lo, b.hi, e);
    return ds_renorm(p, e);
}

#define REG 2304   // floats per As/Bs region per half

// AGEN: 1 = stencil from X/Y (G1); 2 = S-gen (G2); 3 = STp-gen (G4);
//       4 = (Cq0+..+Cq15) ⊙ W fused load (G3)
// BGEN: 1 = sum8(PE)+sgn*sum8(PO); 2 = sum4(Ulow)+sgn*sum4(Uhigh);
//       3 = STp-gen (G1); 4 = S-gen (G3)
// STM:  0 plain float2 store; 1 strided shifted store (row 2*k2+1+par, col+1)
// Generated operands are produced BEFORE grid_bar(ep) (ep==0: no barrier);
// global operands are loaded after it.
template<int BM, int BK, int TM, int AGEN, int BGEN, int STM>
__device__ void gemm_ss(const float* __restrict__ X, const float* __restrict__ Y,
                        float* __restrict__ Cout, int ldc,
                        int mT, int nT, int kbase,
                        float sgn, int par, unsigned ep,
                        int tid, int barid,
                        float* __restrict__ As, float* __restrict__ Bs) {
    constexpr int AW  = BM + 4;            // As row stride
    constexpr int EA  = BM * BK / 256;     // A elems per thread
    constexpr int TPR = 256 / BM;          // threads per A row
    constexpr int RB  = BK / 16;           // B float2 rows per thread
    const int tx = tid & 15, ty = tid >> 4;
    const int am = tid / TPR;
    const int ak = (tid % TPR) * (BK / TPR);
    const int bk = tid >> 4;
    const int bn = (tid & 15) * 2;
    const int nb = (BGEN == 1) ? ((nT < 64 ? nT : nT - 64) + bn) : 0;

    float ra[EA]; float2 rb[RB];

    // ---- generated operands (no cross-CTA deps) ----
    if (AGEN == 1) {                       // B-stencil tile rows m, cols 2k+par
        const int m = mT + am;
        const int jbase = 2 * (kbase + ak) + par;
        const bool mok = (m < 510);
        float emid[EA + 1];
#pragma unroll
        for (int q = 0; q <= EA; q++) {
            int c = jbase + 2 * q;
            emid[q] = (mok && c < 512) ? gaussv(X, Y, (m + 1) * 512 + c) : 0.f;
        }
#pragma unroll
        for (int q = 0; q < EA; q++) {
            int c = jbase + 1 + 2 * q;
            float em = 0.f, epv = 0.f;
            if (mok && c < 512) {
                em  = gaussv(X, Y, m * 512 + c);
                epv = gaussv(X, Y, (m + 2) * 512 + c);
            }
            int j = jbase + 2 * q;
            ra[q] = (mok && j < 510)
                  ? 0.25f * (((em + epv) + emid[q]) + emid[q + 1]) : 0.f;
        }
    } else if (AGEN == 2) {                // S[m][c], m mode / c grid col
        const int m = modeI(mT + am);
#pragma unroll
        for (int q = 0; q < EA; q++) {
            int c = kbase + ak + q;
            ra[q] = (c < 510) ? sbasis(m, c + 1) : 0.f;
        }
    } else if (AGEN == 3) {                // STp[k2][ii-1]
        const int k2 = mT + am;
        const int mult = 2 * k2 + 1 + par;
#pragma unroll
        for (int q = 0; q < EA; q++)
            ra[q] = (k2 < 255) ? sbasis(kbase + ak + q + 1, mult) : 0.f;
    }
    if (BGEN == 3) {                       // STp rows k2=kbase.., cols modes
#pragma unroll
        for (int r = 0; r < RB; r++) {
            int k2 = kbase + bk + 16 * r;
            if (k2 < 255) {
                int mult = 2 * k2 + 1 + par;
                rb[r].x = sbasis(nT + bn + 1, mult);
                rb[r].y = sbasis(nT + bn + 2, mult);
            } else { rb[r].x = 0.f; rb[r].y = 0.f; }
        }
    } else if (BGEN == 4) {                // S rows = modes, cols = grid col
#pragma unroll
        for (int r = 0; r < RB; r++) {
            int mm = modeI(kbase + bk + 16 * r);
            int c0 = nT + bn;
            rb[r].x = (c0     < 510) ? sbasis(mm, c0 + 1) : 0.f;
            rb[r].y = (c0 + 1 < 510) ? sbasis(mm, c0 + 2) : 0.f;
        }
    }

    if (ep) grid_bar(ep);                  // generated work hides under wait

    // ---- global operands (producer-ordered by the barrier above) ----
    if (AGEN == 4) {                       // (sum Cq) ⊙ W
#pragma unroll
        for (int q = 0; q < EA / 2; q++) {
            int k = kbase + ak + q * 2;
            const float* p = g_Cq + (mT + am) * 128 + k;
            float2 s = *(const float2*)p;
#pragma unroll
            for (int h = 1; h < 16; h++) {
                float2 c = *(const float2*)(p + h * 16384);
                s.x += c.x; s.y += c.y;
            }
            float2 w = *(const float2*)&g_W[(mT + am) * 128 + k];
            ra[q * 2] = s.x * w.x; ra[q * 2 + 1] = s.y * w.y;
        }
    }
    if (BGEN == 1) {                       // sum8(PE) + sgn*sum8(PO)
#pragma unroll
        for (int r = 0; r < RB; r++) {
            int k = kbase + bk + 16 * r;
            const float* pe = g_PE + k * 64 + nb;
            const float* po = g_PO + k * 64 + nb;
            float ex = 0.f, ey = 0.f, ox = 0.f, oy = 0.f;
#pragma unroll
            for (int h = 0; h < 8; h++) {
                float2 e = *(const float2*)(pe + h * 32768);
                float2 o = *(const float2*)(po + h * 32768);
                ex += e.x; ey += e.y; ox += o.x; oy += o.y;
            }
            rb[r].x = fmaf(sgn, ox, ex); rb[r].y = fmaf(sgn, oy, ey);
        }
    } else if (BGEN == 2) {                // sum4(Ulow) + sgn*sum4(Uhigh)
#pragma unroll
        for (int r = 0; r < RB; r++) {
            int k = kbase + bk + 16 * r;
            const float* pl = g_U + k * 512 + nT + bn;
            float lx = 0.f, ly = 0.f, hx = 0.f, hy = 0.f;
#pragma unroll
            for (int h = 0; h < 4; h++) {
                float2 l  = *(const float2*)(pl + h * 65536);
                float2 hh = *(const float2*)(pl + 64 * 512 + h * 65536);
                lx += l.x; ly += l.y; hx += hh.x; hy += hh.y;
            }
            rb[r].x = fmaf(sgn, hx, lx); rb[r].y = fmaf(sgn, hy, ly);
        }
    }

    // stash (smem reuse vs previous stage protected by grid_bar's syncthreads;
    // G1 has no predecessor)
#pragma unroll
    for (int j = 0; j < EA; j++) As[(ak + j) * AW + am] = ra[j];   // transposed
#pragma unroll
    for (int r = 0; r < RB; r++) *(float2*)&Bs[(bk + 16 * r) * 36 + bn] = rb[r];
    bar_named(barid);

    float acc[TM][2];
#pragma unroll
    for (int i = 0; i < TM; i++) { acc[i][0] = 0.0f; acc[i][1] = 0.0f; }
#pragma unroll
    for (int kk = 0; kk < BK; kk++) {
        float a[TM];
        if (TM == 4) {
            float4 v = *(const float4*)&As[kk * AW + ty * 4];
            a[0] = v.x; a[1] = v.y; a[2] = v.z; a[3] = v.w;
        } else {
            float2 v = *(const float2*)&As[kk * AW + ty * 2];
            a[0] = v.x; a[1] = v.y;
        }
        float2 b = *(const float2*)&Bs[kk * 36 + tx * 2];
#pragma unroll
        for (int i = 0; i < TM; i++) {
            acc[i][0] += a[i] * b.x;
            acc[i][1] += a[i] * b.y;
        }
    }

    if (STM == 1) {
#pragma unroll
        for (int i = 0; i < TM; i++) {
            int k2 = mT + ty * TM + i;
            if (k2 >= 255) continue;
            int rr = 2 * k2 + 1 + par;             // +1 output shift
#pragma unroll
            for (int j = 0; j < 2; j++) {
                int c2 = nT + tx * 2 + j;
                if (c2 < 510) Cout[rr * 512 + c2 + 1] = acc[i][j];
            }
        }
    } else {
#pragma unroll
        for (int i = 0; i < TM; i++)
            *(float2*)&Cout[(size_t)(mT + ty * TM + i) * ldc + nT + tx * 2] =
                make_float2(acc[i][0], acc[i][1]);
    }
}

__global__ void __launch_bounds__(TPB, 1)
jacobi_fused(const float* __restrict__ X, const float* __restrict__ Y,
             float* __restrict__ out) {
    __shared__ float pool[2][2 * REG];             // [half][As | Bs]
    const int cta = blockIdx.x, tid = threadIdx.x;
    const int gtid = cta * TPB + tid;
    const int half = tid >> 8;
    const int htid = tid & 255;
    const int barid = 1 + half;
    float* myAs = pool[half];
    float* myBs = pool[half] + REG;
    const unsigned eb = __ldcg(&g_bar[NCTA]);      // epoch base (persists)
    const int jid = cta * 2 + half;                // 0..255

    // cds seeds (ONLY fp64: 64 cospi on CTA0; W-readers ordered by bar eb+1)
    if (gtid < 64) {
        double c = cospi((double)(gtid + 1) / 511.0);
        float hi = (float)c;
        float lo = (float)(c - (double)hi);
        g_cds[gtid] = make_float2(hi, lo);
    }
    // out boundary (disjoint from G4's interior writes)
    if (gtid < 2048) {
        int e = gtid >> 9, t = gtid & 511;
        if      (e == 0) out[t] = 0.0f;
        else if (e == 1) out[511 * 512 + t] = 0.0f;
        else if (e == 2) out[t * 512] = 0.0f;
        else             out[t * 512 + 511] = 0.0f;
    }

    // ---- G1: PE/PO = stencil(X,Y) x STp-gen (NO grid barrier needed) ----
    {
        int p = jid & 1, t = (jid >> 1) & 15, h = jid >> 5;
        float* Cop = (p ? g_PO : g_PE) + h * 32768;
        gemm_ss<64, 32, 4, 1, 3, 0>(X, Y, Cop, 64,
                                    (t >> 1) * 64, (t & 1) * 32, h * 32,
                                    0.f, p, 0u, htid, barid, myAs, myBs);
    }
    grid_bar(eb + 1);

    // ---- W in DS fp32 on CTAs 32..63 (cds ordered by eb+1; readers by eb+2) ----
    if (cta >= 32 && cta < 64) {
        int i = (cta - 32) * 512 + tid;            // 16384 entries
        int m = i >> 7, n = i & 127;
        float2 a2 = g_cds[(m < 64) ? m : (m - 64)];
        float2 b2 = g_cds[(n < 64) ? n : (n - 64)];
        DS cm = (m < 64) ? DS{a2.x, a2.y} : DS{-a2.x, -a2.y};
        DS cn = (n < 64) ? DS{b2.x, b2.y} : DS{-b2.x, -b2.y};
        DS lam = ds_add(cm, cn);
        lam.hi *= 0.5f; lam.lo *= 0.5f;
        DS r{1.0f, 0.0f}, b = lam;
        int e = 999;
        while (e) {
            if (e & 1) r = ds_mul(r, b);
            b = ds_mul(b, b);
            e >>= 1;
        }
        const DS K{1.5318627e-05f, -5.6477107e-13f};   // 4/511^2 split
        r = ds_mul(r, K);
        g_W[i] = r.hi + r.lo;
    }

    // ---- G2: Cq = S-gen x (PE +/- PO fused8); gen before bar eb+2? no —
    //      bar already passed (eb+1); generated A hides under nothing, tiny ----
    {
        int t = jid >> 4, h = jid & 15;
        int mT = (t >> 2) * 32, nT = (t & 3) * 32;
        float sgn = (nT < 64) ? 1.0f : -1.0f;
        gemm_ss<32, 32, 2, 2, 1, 0>(X, Y, g_Cq + h * 16384, 128,
                                    mT, nT, h * 32,
                                    sgn, 0, 0u, htid, barid, myAs, myBs);
    }

    // ---- G3: U = ((sum Cq16) ⊙ W) x S-gen; S-gen before bar eb+2 ----
    {
        int t = jid >> 2, h = jid & 3;
        gemm_ss<32, 32, 2, 4, 4, 0>(X, Y, g_U + h * 65536, 512,
                                    (t >> 4) * 32, (t & 15) * 32, h * 32,
                                    0.f, 0, eb + 2, htid, barid, myAs, myBs);
    }

    // ---- G4: out = STp-gen x (U fused4 +/-); gen before bar eb+3 ----
    {
        int eo = jid >> 7, t = jid & 127;
        float sgn = eo ? -1.0f : 1.0f;
        gemm_ss<32, 64, 2, 3, 2, 1>(X, Y, out, 512,
                                    (t >> 4) * 32, (t & 15) * 32, 0,
                                    sgn, eo, eb + 3, htid, barid, myAs, myBs);
    }
}

extern "C" void kernel_launch(void* const* d_in, const int* in_sizes, int n_in,
                              void* d_out, int out_size) {
    (void)in_sizes; (void)n_in; (void)out_size;
    jacobi_fused<<<NCTA, TPB>>>((const float*)d_in[0], (const float*)d_in[1],
                                (float*)d_out);
}